// round 6
// baseline (speedup 1.0000x reference)
#include <cuda_runtime.h>
#include <cstdint>

// DifferentiableDAG: B*T independent 8-step log-space DAG executions.
// One thread per element. Warp-private TRIPLE-buffered cp.async pipeline,
// prefetch distance 2 (wait_group 2): each warp keeps two future chunks in
// flight so DRAM latency is hidden behind two compute steps.
// Row stride 23 floats (odd => conflict-free LDS); smem 35.3KB/block, 6 blocks/SM.
// (R6 == R5 resubmitted: R5 bench was an infra failure, kernel never ran.)

constexpr int TPB  = 128;
constexpr int ST   = 23;              // floats per smem row (23 used; odd => conflict-free)
constexpr int WBUF = 32 * ST;         // floats per warp per buffer (736)
constexpr int BUF  = 4 * WBUF;        // per-block buffer (4 warps)

__device__ __forceinline__ void cp_async4(uint32_t saddr, const void* gaddr) {
    asm volatile("cp.async.ca.shared.global [%0], [%1], 4;\n" :: "r"(saddr), "l"(gaddr));
}
__device__ __forceinline__ void cp_commit() { asm volatile("cp.async.commit_group;\n"); }
template<int N>
__device__ __forceinline__ void cp_wait() { asm volatile("cp.async.wait_group %0;\n" :: "n"(N) : "memory"); }

// clip_log(x) = 15*tanh(x/15) via (1-e^{-2z})/(1+e^{-2z})
__device__ __forceinline__ float clip_log(float x) {
    float a = fabsf(x) * (2.0f / 15.0f);
    float t = __expf(-a);
    float u = __fdividef(1.0f - t, 1.0f + t);
    return copysignf(15.0f * u, x);
}

// Stage step S for this warp's 32 elements: p1[0..S], p2[0..S], pop[0..4].
template<int S>
__device__ __forceinline__ void issue_chunk(
    uint32_t sbuf, const float* __restrict__ p1, const float* __restrict__ p2,
    const float* __restrict__ pop, int W0, int lane, int elems)
{
    constexpr int NF = S + 1;
#pragma unroll
    for (int k = 0; k < NF; k++) {
        int i = lane + 32 * k;            // 0 .. 32*NF-1
        int e = i / NF, q = i - NF * e;
        if (W0 + e < elems) {
            int g = (W0 + e) * 72 + S * 9 + q;
            cp_async4(sbuf + 4u * (uint32_t)(e * ST + q),     p1 + g);
            cp_async4(sbuf + 4u * (uint32_t)(e * ST + 9 + q), p2 + g);
        }
    }
#pragma unroll
    for (int k = 0; k < 5; k++) {
        int i = lane + 32 * k;
        int e = i / 5, q = i - 5 * e;
        if (W0 + e < elems)
            cp_async4(sbuf + 4u * (uint32_t)(e * ST + 18 + q),
                      pop + (W0 + e) * 40 + S * 5 + q);
    }
}

template<int S>
__device__ __forceinline__ void step_compute(
    const float* __restrict__ row, float (&sg)[9], float (&lg)[9], float& acc)
{
    // ---- dot products over live nodes 0..S ----
    float s1v = 0.f, l1v = 0.f, s2v = 0.f, l2v = 0.f;
#pragma unroll
    for (int n = 0; n <= S; n++) {
        float a = row[n];
        float b = row[9 + n];
        s1v = fmaf(a, sg[n], s1v);
        l1v = fmaf(a, lg[n], l1v);
        s2v = fmaf(b, sg[n], s2v);
        l2v = fmaf(b, lg[n], l2v);
    }
    float po0 = row[18], po1 = row[19], po2 = row[20], po3 = row[21], po4 = row[22];

    // ---- shared log-magnitude pieces (identical for add and sub) ----
    float dlt    = l1v - l2v;
    float m      = fmaxf(l1v, l2v);
    float l_same = clip_log(m + __logf(1.0f + __expf(-fabsf(dlt))));
    bool  bigger = (l1v >= l2v);
    float big_l  = bigger ? l1v : l2v;
    float small_l = bigger ? l2v : l1v;
    float delta  = fminf(fmaxf(small_l - big_l, -15.0f), -0.001f);
    float diffv  = __logf(1.0f - __expf(delta));     // log1p(-exp(delta)), arg in [1e-3,1)
    bool  zr     = (small_l == big_l);
    float new_l  = zr ? 0.0f : (big_l + diffv);

    bool  z1 = (s1v == 0.0f), z2 = (s2v == 0.0f);
    float prod = s1v * s2v;
    float s_sgn1 = (s1v > 0.f) ? 1.f : ((s1v < 0.f) ? -1.f : 0.f);

    // ---- ADD ----
    float sa = 0.f, la = 0.f;
    {
        bool same_sign = (prod > 0.0f);
        float big_s = bigger ? s1v : s2v;
        float new_s = zr ? 0.0f : big_s;
        if (!z1 &&  z2) { sa = s1v; la = l1v; }
        if ( z1 && !z2) { sa = s2v; la = l2v; }
        if (!z1 && !z2) {
            if (same_sign) { sa = s_sgn1; la = l_same; }
            else           { sa = new_s;  la = new_l;  }
        }
        la = clip_log(la);
    }
    // ---- SUB (sy = -s2v) ----
    float sb = 0.f, lb = 0.f;
    {
        bool same_sign = (prod < 0.0f);
        float sy = -s2v;
        float big_s = bigger ? s1v : sy;
        float new_s = zr ? 0.0f : big_s;
        if (!z1 &&  z2) { sb = s1v; lb = l1v; }
        if ( z1 && !z2) { sb = sy;  lb = l2v; }
        if (!z1 && !z2) {
            if (same_sign) { sb = s_sgn1; lb = l_same; }
            else           { sb = new_s;  lb = new_l;  }
        }
        lb = clip_log(lb);
    }
    // ---- MUL / DIV / ID ----
    float lm = clip_log(l1v + l2v);
    float ld = clip_log(dlt);

    // ---- probability mix ----
    float s_mix = po0 * sa;
    s_mix = fmaf(po1, sb,   s_mix);
    s_mix = fmaf(po2, prod, s_mix);
    s_mix = fmaf(po3, prod, s_mix);
    s_mix = fmaf(po4, s1v,  s_mix);
    float l_mix = po0 * la;
    l_mix = fmaf(po1, lb,  l_mix);
    l_mix = fmaf(po2, lm,  l_mix);
    l_mix = fmaf(po3, ld,  l_mix);
    l_mix = fmaf(po4, l1v, l_mix);
    l_mix = clip_log(l_mix);

    // ---- incremental RMS rescale over logs[0..S] + l_mix ----
    float cur = fmaf(l_mix, l_mix, acc);
    constexpr float inv = 1.0f / (float)(S + 2);
    float r     = rsqrtf(cur * inv + 1e-6f);
    float scale = fminf(15.0f * r, 1.0f);
    l_mix *= scale;

    sg[S + 1] = s_mix;
    lg[S + 1] = l_mix;
    acc = fmaf(l_mix, l_mix, acc);
}

__global__ void __launch_bounds__(TPB, 6)
dag_kernel(const float* __restrict__ isgn, const float* __restrict__ ilog,
           const float* __restrict__ p1,   const float* __restrict__ p2,
           const float* __restrict__ pop,  float* __restrict__ out, int elems)
{
    __shared__ float smem[3 * BUF];      // 35,328 B: triple buffer

    const int t    = threadIdx.x;
    const int lane = t & 31;
    const int w    = t >> 5;
    const int E0   = blockIdx.x * TPB;
    const int W0   = E0 + w * 32;        // this warp's first element
    const int e    = W0 + lane;          // this thread's element

    // Hoist the two initial scalar loads so their latency overlaps the prologue.
    float seed_s = 0.f, seed_l = 0.f;
    if (e < elems) {
        seed_s = isgn[(size_t)e * 9];
        seed_l = ilog[(size_t)e * 9];
    }

    uint32_t sA = (uint32_t)__cvta_generic_to_shared(smem) + 4u * (uint32_t)(w * WBUF);
    uint32_t sB = sA + 4u * BUF;
    uint32_t sC = sB + 4u * BUF;

    // Prologue: chunks 0,1,2 in flight (prefetch distance 2).
    issue_chunk<0>(sA, p1, p2, pop, W0, lane, elems); cp_commit();
    issue_chunk<1>(sB, p1, p2, pop, W0, lane, elems); cp_commit();
    issue_chunk<2>(sC, p1, p2, pop, W0, lane, elems); cp_commit();

    // Only node 0 of the initial state is nonzero (by construction).
    float sg[9], lg[9];
#pragma unroll
    for (int j = 0; j < 9; j++) { sg[j] = 0.f; lg[j] = 0.f; }
    sg[0] = seed_s;
    lg[0] = seed_l;
    float acc = lg[0] * lg[0];

    const float* rowA = smem + w * WBUF + lane * ST;
    const float* rowB = rowA + BUF;
    const float* rowC = rowB + BUF;

    // s=0: wait g0, compute A, refill A with chunk 3
    cp_wait<2>(); __syncwarp();
    step_compute<0>(rowA, sg, lg, acc);
    __syncwarp();
    issue_chunk<3>(sA, p1, p2, pop, W0, lane, elems); cp_commit();
    // s=1
    cp_wait<2>(); __syncwarp();
    step_compute<1>(rowB, sg, lg, acc);
    __syncwarp();
    issue_chunk<4>(sB, p1, p2, pop, W0, lane, elems); cp_commit();
    // s=2
    cp_wait<2>(); __syncwarp();
    step_compute<2>(rowC, sg, lg, acc);
    __syncwarp();
    issue_chunk<5>(sC, p1, p2, pop, W0, lane, elems); cp_commit();
    // s=3
    cp_wait<2>(); __syncwarp();
    step_compute<3>(rowA, sg, lg, acc);
    __syncwarp();
    issue_chunk<6>(sA, p1, p2, pop, W0, lane, elems); cp_commit();
    // s=4
    cp_wait<2>(); __syncwarp();
    step_compute<4>(rowB, sg, lg, acc);
    __syncwarp();
    issue_chunk<7>(sB, p1, p2, pop, W0, lane, elems); cp_commit();
    // s=5 (no more issues; pending g5,g6,g7)
    cp_wait<2>(); __syncwarp();
    step_compute<5>(rowC, sg, lg, acc);
    // s=6 (pending g6,g7)
    cp_wait<1>(); __syncwarp();
    step_compute<6>(rowA, sg, lg, acc);
    // s=7 (drain)
    cp_wait<0>(); __syncwarp();
    step_compute<7>(rowB, sg, lg, acc);

    if (e < elems)
        out[e] = sg[8] * __expf(lg[8]);
}

extern "C" void kernel_launch(void* const* d_in, const int* in_sizes, int n_in,
                              void* d_out, int out_size)
{
    const float* isgn = (const float*)d_in[0];
    const float* ilog = (const float*)d_in[1];
    const float* p1   = (const float*)d_in[2];
    const float* p2   = (const float*)d_in[3];
    const float* pop  = (const float*)d_in[4];
    float* out = (float*)d_out;

    int elems  = in_sizes[0] / 9;               // B*T
    int blocks = (elems + TPB - 1) / TPB;
    dag_kernel<<<blocks, TPB>>>(isgn, ilog, p1, p2, pop, out, elems);
}

// round 8
// speedup vs baseline: 1.5428x; 1.5428x over previous
#include <cuda_runtime.h>
#include <cstdint>

// DifferentiableDAG: B*T independent 8-step log-space DAG executions.
// R8 == R7 resubmitted (R7 bench was an infra failure; kernel never ran).
// TWO elements per thread (64 per warp). Warp-private DOUBLE-buffered
// cp.async staging (distance 1 — the R4-proven envelope; depth 3 flooded the
// L1tex queue in R6). 2 elems/thread halves exposed wait per element and
// doubles ILP across the serial MUFU chains.
// ST=23 (odd => conflict-free LDS). smem 47.1KB/block static, 4 blocks/SM.

constexpr int TPB  = 128;
constexpr int ST   = 23;               // floats per smem row (23 used)
constexpr int EPW  = 64;               // elements per warp
constexpr int WBUF = EPW * ST;         // floats per warp per buffer (1472)
constexpr int BUF  = 4 * WBUF;         // per-block per-buffer (4 warps)

__device__ __forceinline__ void cp_async4(uint32_t saddr, const void* gaddr) {
    asm volatile("cp.async.ca.shared.global [%0], [%1], 4;\n" :: "r"(saddr), "l"(gaddr));
}
__device__ __forceinline__ void cp_commit() { asm volatile("cp.async.commit_group;\n"); }
template<int N>
__device__ __forceinline__ void cp_wait() { asm volatile("cp.async.wait_group %0;\n" :: "n"(N) : "memory"); }

// clip_log(x) = 15*tanh(x/15) via (1-e^{-2z})/(1+e^{-2z})
__device__ __forceinline__ float clip_log(float x) {
    float a = fabsf(x) * (2.0f / 15.0f);
    float t = __expf(-a);
    float u = __fdividef(1.0f - t, 1.0f + t);
    return copysignf(15.0f * u, x);
}

// Stage step S for this warp's 64 elements: p1[0..S], p2[0..S], pop[0..4].
template<int S>
__device__ __forceinline__ void issue_chunk(
    uint32_t sbuf, const float* __restrict__ p1, const float* __restrict__ p2,
    const float* __restrict__ pop, int W0, int lane, int elems)
{
    constexpr int NF = S + 1;
#pragma unroll
    for (int k = 0; k < 2 * NF; k++) {     // 64*NF items over 32 lanes
        int i = lane + 32 * k;             // 0 .. 64*NF-1
        int e = i / NF, q = i - NF * e;
        if (W0 + e < elems) {
            int g = (W0 + e) * 72 + S * 9 + q;
            cp_async4(sbuf + 4u * (uint32_t)(e * ST + q),     p1 + g);
            cp_async4(sbuf + 4u * (uint32_t)(e * ST + 9 + q), p2 + g);
        }
    }
#pragma unroll
    for (int k = 0; k < 10; k++) {         // 64*5 items over 32 lanes
        int i = lane + 32 * k;
        int e = i / 5, q = i - 5 * e;
        if (W0 + e < elems)
            cp_async4(sbuf + 4u * (uint32_t)(e * ST + 18 + q),
                      pop + (W0 + e) * 40 + S * 5 + q);
    }
}

template<int S>
__device__ __forceinline__ void step_compute(
    const float* __restrict__ row, float (&sg)[9], float (&lg)[9], float& acc)
{
    // ---- dot products over live nodes 0..S ----
    float s1v = 0.f, l1v = 0.f, s2v = 0.f, l2v = 0.f;
#pragma unroll
    for (int n = 0; n <= S; n++) {
        float a = row[n];
        float b = row[9 + n];
        s1v = fmaf(a, sg[n], s1v);
        l1v = fmaf(a, lg[n], l1v);
        s2v = fmaf(b, sg[n], s2v);
        l2v = fmaf(b, lg[n], l2v);
    }
    float po0 = row[18], po1 = row[19], po2 = row[20], po3 = row[21], po4 = row[22];

    // ---- shared log-magnitude pieces (identical for add and sub) ----
    float dlt    = l1v - l2v;
    float m      = fmaxf(l1v, l2v);
    float l_same = clip_log(m + __logf(1.0f + __expf(-fabsf(dlt))));
    bool  bigger = (l1v >= l2v);
    float big_l  = bigger ? l1v : l2v;
    float small_l = bigger ? l2v : l1v;
    float delta  = fminf(fmaxf(small_l - big_l, -15.0f), -0.001f);
    float diffv  = __logf(1.0f - __expf(delta));     // log1p(-exp(delta)), arg in [1e-3,1)
    bool  zr     = (small_l == big_l);
    float new_l  = zr ? 0.0f : (big_l + diffv);

    bool  z1 = (s1v == 0.0f), z2 = (s2v == 0.0f);
    float prod = s1v * s2v;
    float s_sgn1 = (s1v > 0.f) ? 1.f : ((s1v < 0.f) ? -1.f : 0.f);

    // ---- ADD ----
    float sa = 0.f, la = 0.f;
    {
        bool same_sign = (prod > 0.0f);
        float big_s = bigger ? s1v : s2v;
        float new_s = zr ? 0.0f : big_s;
        if (!z1 &&  z2) { sa = s1v; la = l1v; }
        if ( z1 && !z2) { sa = s2v; la = l2v; }
        if (!z1 && !z2) {
            if (same_sign) { sa = s_sgn1; la = l_same; }
            else           { sa = new_s;  la = new_l;  }
        }
        la = clip_log(la);
    }
    // ---- SUB (sy = -s2v) ----
    float sb = 0.f, lb = 0.f;
    {
        bool same_sign = (prod < 0.0f);
        float sy = -s2v;
        float big_s = bigger ? s1v : sy;
        float new_s = zr ? 0.0f : big_s;
        if (!z1 &&  z2) { sb = s1v; lb = l1v; }
        if ( z1 && !z2) { sb = sy;  lb = l2v; }
        if (!z1 && !z2) {
            if (same_sign) { sb = s_sgn1; lb = l_same; }
            else           { sb = new_s;  lb = new_l;  }
        }
        lb = clip_log(lb);
    }
    // ---- MUL / DIV / ID ----
    float lm = clip_log(l1v + l2v);
    float ld = clip_log(dlt);

    // ---- probability mix ----
    float s_mix = po0 * sa;
    s_mix = fmaf(po1, sb,   s_mix);
    s_mix = fmaf(po2, prod, s_mix);
    s_mix = fmaf(po3, prod, s_mix);
    s_mix = fmaf(po4, s1v,  s_mix);
    float l_mix = po0 * la;
    l_mix = fmaf(po1, lb,  l_mix);
    l_mix = fmaf(po2, lm,  l_mix);
    l_mix = fmaf(po3, ld,  l_mix);
    l_mix = fmaf(po4, l1v, l_mix);
    l_mix = clip_log(l_mix);

    // ---- incremental RMS rescale over logs[0..S] + l_mix ----
    float cur = fmaf(l_mix, l_mix, acc);
    constexpr float inv = 1.0f / (float)(S + 2);
    float r     = rsqrtf(cur * inv + 1e-6f);
    float scale = fminf(15.0f * r, 1.0f);
    l_mix *= scale;

    sg[S + 1] = s_mix;
    lg[S + 1] = l_mix;
    acc = fmaf(l_mix, l_mix, acc);
}

__global__ void __launch_bounds__(TPB, 4)
dag_kernel(const float* __restrict__ isgn, const float* __restrict__ ilog,
           const float* __restrict__ p1,   const float* __restrict__ p2,
           const float* __restrict__ pop,  float* __restrict__ out, int elems)
{
    __shared__ float smem[2 * BUF];      // 47,104 B: double buffer, 64 elems/warp

    const int t    = threadIdx.x;
    const int lane = t & 31;
    const int w    = t >> 5;
    const int W0   = (blockIdx.x * 4 + w) * EPW;   // this warp's first element
    const int eA   = W0 + lane;                    // thread's element A
    const int eB   = W0 + lane + 32;               // thread's element B

    // Hoist initial scalar loads; latency overlaps the prologue.
    float seedAs = 0.f, seedAl = 0.f, seedBs = 0.f, seedBl = 0.f;
    if (eA < elems) { seedAs = isgn[(size_t)eA * 9]; seedAl = ilog[(size_t)eA * 9]; }
    if (eB < elems) { seedBs = isgn[(size_t)eB * 9]; seedBl = ilog[(size_t)eB * 9]; }

    uint32_t sA = (uint32_t)__cvta_generic_to_shared(smem) + 4u * (uint32_t)(w * WBUF);
    uint32_t sB = sA + 4u * BUF;

    // Prologue: chunks 0 and 1 in flight (distance 1).
    issue_chunk<0>(sA, p1, p2, pop, W0, lane, elems); cp_commit();
    issue_chunk<1>(sB, p1, p2, pop, W0, lane, elems); cp_commit();

    // Only node 0 of the initial state is nonzero (by construction).
    float sgA[9], lgA[9], sgB[9], lgB[9];
#pragma unroll
    for (int j = 0; j < 9; j++) { sgA[j] = 0.f; lgA[j] = 0.f; sgB[j] = 0.f; lgB[j] = 0.f; }
    sgA[0] = seedAs; lgA[0] = seedAl;
    sgB[0] = seedBs; lgB[0] = seedBl;
    float accA = lgA[0] * lgA[0];
    float accB = lgB[0] * lgB[0];

    const float* rowA0 = smem + w * WBUF + lane * ST;          // elem A, buffer 0
    const float* rowB0 = rowA0 + 32 * ST;                      // elem B, buffer 0
    const float* rowA1 = rowA0 + BUF;                          // buffer 1
    const float* rowB1 = rowB0 + BUF;

    // s=0
    cp_wait<1>(); __syncwarp();
    step_compute<0>(rowA0, sgA, lgA, accA);
    step_compute<0>(rowB0, sgB, lgB, accB);
    __syncwarp();
    issue_chunk<2>(sA, p1, p2, pop, W0, lane, elems); cp_commit();
    // s=1
    cp_wait<1>(); __syncwarp();
    step_compute<1>(rowA1, sgA, lgA, accA);
    step_compute<1>(rowB1, sgB, lgB, accB);
    __syncwarp();
    issue_chunk<3>(sB, p1, p2, pop, W0, lane, elems); cp_commit();
    // s=2
    cp_wait<1>(); __syncwarp();
    step_compute<2>(rowA0, sgA, lgA, accA);
    step_compute<2>(rowB0, sgB, lgB, accB);
    __syncwarp();
    issue_chunk<4>(sA, p1, p2, pop, W0, lane, elems); cp_commit();
    // s=3
    cp_wait<1>(); __syncwarp();
    step_compute<3>(rowA1, sgA, lgA, accA);
    step_compute<3>(rowB1, sgB, lgB, accB);
    __syncwarp();
    issue_chunk<5>(sB, p1, p2, pop, W0, lane, elems); cp_commit();
    // s=4
    cp_wait<1>(); __syncwarp();
    step_compute<4>(rowA0, sgA, lgA, accA);
    step_compute<4>(rowB0, sgB, lgB, accB);
    __syncwarp();
    issue_chunk<6>(sA, p1, p2, pop, W0, lane, elems); cp_commit();
    // s=5
    cp_wait<1>(); __syncwarp();
    step_compute<5>(rowA1, sgA, lgA, accA);
    step_compute<5>(rowB1, sgB, lgB, accB);
    __syncwarp();
    issue_chunk<7>(sB, p1, p2, pop, W0, lane, elems); cp_commit();
    // s=6
    cp_wait<1>(); __syncwarp();
    step_compute<6>(rowA0, sgA, lgA, accA);
    step_compute<6>(rowB0, sgB, lgB, accB);
    // s=7 (drain)
    cp_wait<0>(); __syncwarp();
    step_compute<7>(rowA1, sgA, lgA, accA);
    step_compute<7>(rowB1, sgB, lgB, accB);

    if (eA < elems) out[eA] = sgA[8] * __expf(lgA[8]);
    if (eB < elems) out[eB] = sgB[8] * __expf(lgB[8]);
}

extern "C" void kernel_launch(void* const* d_in, const int* in_sizes, int n_in,
                              void* d_out, int out_size)
{
    const float* isgn = (const float*)d_in[0];
    const float* ilog = (const float*)d_in[1];
    const float* p1   = (const float*)d_in[2];
    const float* p2   = (const float*)d_in[3];
    const float* pop  = (const float*)d_in[4];
    float* out = (float*)d_out;

    int elems  = in_sizes[0] / 9;                       // B*T
    int blocks = (elems + TPB * 2 - 1) / (TPB * 2);     // 2 elems per thread
    dag_kernel<<<blocks, TPB>>>(isgn, ilog, p1, p2, pop, out, elems);
}

// round 10
// speedup vs baseline: 1.5993x; 1.0366x over previous
#include <cuda_runtime.h>
#include <cstdint>

// DifferentiableDAG: B*T independent 8-step log-space DAG executions.
// R10 == R9 resubmitted (R9 bench was an infra failure; kernel never ran).
// R9 = R4 envelope (1 elem/thread, warp-private DOUBLE buffer, distance 1)
// + register/instruction diet (shared exp via monotone clamp, CSE, copysign,
//   warp-level bounds fast path)
// + __launch_bounds__(128,7): 72-reg cap -> 7 blocks = 28 warps/SM.

constexpr int TPB  = 128;
constexpr int ST   = 23;              // floats per smem row (odd => conflict-free)
constexpr int WBUF = 32 * ST;         // floats per warp per buffer (736)
constexpr int BUF  = 4 * WBUF;        // per-block per-buffer (4 warps)

__device__ __forceinline__ void cp_async4(uint32_t saddr, const void* gaddr) {
    asm volatile("cp.async.ca.shared.global [%0], [%1], 4;\n" :: "r"(saddr), "l"(gaddr));
}
__device__ __forceinline__ void cp_commit() { asm volatile("cp.async.commit_group;\n"); }
template<int N>
__device__ __forceinline__ void cp_wait() { asm volatile("cp.async.wait_group %0;\n" :: "n"(N) : "memory"); }

// clip_log(x) = 15*tanh(x/15) via (1-e^{-2z})/(1+e^{-2z})
__device__ __forceinline__ float clip_log(float x) {
    float a = fabsf(x) * (2.0f / 15.0f);
    float t = __expf(-a);
    float u = __fdividef(1.0f - t, 1.0f + t);
    return copysignf(15.0f * u, x);
}

// Stage step S for this warp's 32 elements: p1[0..S], p2[0..S], pop[0..4].
// Warp-level bounds fast path: one test instead of 23 per-element predicates.
template<int S>
__device__ __forceinline__ void issue_chunk(
    uint32_t sbuf, const float* __restrict__ p1, const float* __restrict__ p2,
    const float* __restrict__ pop, int W0, int lane, int elems)
{
    constexpr int NF = S + 1;
    if (W0 + 32 <= elems) {            // full warp in range (always, for this grid)
#pragma unroll
        for (int k = 0; k < NF; k++) {
            int i = lane + 32 * k;
            int e = i / NF, q = i - NF * e;
            int g = (W0 + e) * 72 + S * 9 + q;
            cp_async4(sbuf + 4u * (uint32_t)(e * ST + q),     p1 + g);
            cp_async4(sbuf + 4u * (uint32_t)(e * ST + 9 + q), p2 + g);
        }
#pragma unroll
        for (int k = 0; k < 5; k++) {
            int i = lane + 32 * k;
            int e = i / 5, q = i - 5 * e;
            cp_async4(sbuf + 4u * (uint32_t)(e * ST + 18 + q),
                      pop + (W0 + e) * 40 + S * 5 + q);
        }
    } else {
#pragma unroll
        for (int k = 0; k < NF; k++) {
            int i = lane + 32 * k;
            int e = i / NF, q = i - NF * e;
            if (W0 + e < elems) {
                int g = (W0 + e) * 72 + S * 9 + q;
                cp_async4(sbuf + 4u * (uint32_t)(e * ST + q),     p1 + g);
                cp_async4(sbuf + 4u * (uint32_t)(e * ST + 9 + q), p2 + g);
            }
        }
#pragma unroll
        for (int k = 0; k < 5; k++) {
            int i = lane + 32 * k;
            int e = i / 5, q = i - 5 * e;
            if (W0 + e < elems)
                cp_async4(sbuf + 4u * (uint32_t)(e * ST + 18 + q),
                          pop + (W0 + e) * 40 + S * 5 + q);
        }
    }
}

template<int S>
__device__ __forceinline__ void step_compute(
    const float* __restrict__ row, float (&sg)[9], float (&lg)[9], float& acc)
{
    // ---- dot products over live nodes 0..S ----
    float s1v = 0.f, l1v = 0.f, s2v = 0.f, l2v = 0.f;
#pragma unroll
    for (int n = 0; n <= S; n++) {
        float a = row[n];
        float b = row[9 + n];
        s1v = fmaf(a, sg[n], s1v);
        l1v = fmaf(a, lg[n], l1v);
        s2v = fmaf(b, sg[n], s2v);
        l2v = fmaf(b, lg[n], l2v);
    }
    float po0 = row[18], po1 = row[19], po2 = row[20], po3 = row[21], po4 = row[22];

    // ---- shared log-magnitude pieces (identical for add and sub) ----
    float dlt    = l1v - l2v;
    bool  bigger = (l1v >= l2v);
    float big_l  = bigger ? l1v : l2v;        // == max(l1v,l2v)
    float adlt   = fabsf(dlt);
    float E      = __expf(-adlt);             // exp(-|dlt|), one exp shared
    float l_same = clip_log(big_l + __logf(1.0f + E));
    // exp(clamp(-|dlt|, -15, -0.001)) == clamp(E, e^-15, e^-0.001) (monotone)
    float Ec     = fminf(fmaxf(E, 3.0590232e-07f), 0.99900050f);
    float diffv  = __logf(1.0f - Ec);         // log1p(-exp(delta))
    bool  zr     = (adlt == 0.0f);            // small_l == big_l
    float new_l  = zr ? 0.0f : (big_l + diffv);

    bool  z1 = (s1v == 0.0f), z2 = (s2v == 0.0f);
    float prod = s1v * s2v;
    float s_sgn1 = copysignf(1.0f, s1v);      // only consumed where s1v != 0

    // ---- ADD ----
    float sa = 0.f, la = 0.f;
    {
        bool same_sign = (prod > 0.0f);
        float big_s = bigger ? s1v : s2v;
        float new_s = zr ? 0.0f : big_s;
        if (!z1 &&  z2) { sa = s1v; la = l1v; }
        if ( z1 && !z2) { sa = s2v; la = l2v; }
        if (!z1 && !z2) {
            if (same_sign) { sa = s_sgn1; la = l_same; }
            else           { sa = new_s;  la = new_l;  }
        }
        la = clip_log(la);
    }
    // ---- SUB (sy = -s2v) ----
    float sb = 0.f, lb = 0.f;
    {
        bool same_sign = (prod < 0.0f);
        float sy = -s2v;
        float big_s = bigger ? s1v : sy;
        float new_s = zr ? 0.0f : big_s;
        if (!z1 &&  z2) { sb = s1v; lb = l1v; }
        if ( z1 && !z2) { sb = sy;  lb = l2v; }
        if (!z1 && !z2) {
            if (same_sign) { sb = s_sgn1; lb = l_same; }
            else           { sb = new_s;  lb = new_l;  }
        }
        lb = clip_log(lb);
    }
    // ---- MUL / DIV / ID ----
    float lm = clip_log(l1v + l2v);
    float ld = clip_log(dlt);

    // ---- probability mix ----
    float s_mix = po0 * sa;
    s_mix = fmaf(po1, sb,   s_mix);
    s_mix = fmaf(po2, prod, s_mix);
    s_mix = fmaf(po3, prod, s_mix);
    s_mix = fmaf(po4, s1v,  s_mix);
    float l_mix = po0 * la;
    l_mix = fmaf(po1, lb,  l_mix);
    l_mix = fmaf(po2, lm,  l_mix);
    l_mix = fmaf(po3, ld,  l_mix);
    l_mix = fmaf(po4, l1v, l_mix);
    l_mix = clip_log(l_mix);

    // ---- incremental RMS rescale over logs[0..S] + l_mix ----
    float cur = fmaf(l_mix, l_mix, acc);
    constexpr float inv = 1.0f / (float)(S + 2);
    float r     = rsqrtf(cur * inv + 1e-6f);
    float scale = fminf(15.0f * r, 1.0f);
    l_mix *= scale;

    sg[S + 1] = s_mix;
    lg[S + 1] = l_mix;
    acc = fmaf(l_mix, l_mix, acc);
}

__global__ void __launch_bounds__(TPB, 7)
dag_kernel(const float* __restrict__ isgn, const float* __restrict__ ilog,
           const float* __restrict__ p1,   const float* __restrict__ p2,
           const float* __restrict__ pop,  float* __restrict__ out, int elems)
{
    __shared__ float smem[2 * BUF];      // 23,552 B: double buffer

    const int t    = threadIdx.x;
    const int lane = t & 31;
    const int w    = t >> 5;
    const int E0   = blockIdx.x * TPB;
    const int W0   = E0 + w * 32;        // this warp's first element
    const int e    = W0 + lane;          // this thread's element

    // Hoist the two initial scalar loads so their latency overlaps the prologue.
    float seed_s = 0.f, seed_l = 0.f;
    if (e < elems) {
        seed_s = isgn[(size_t)e * 9];
        seed_l = ilog[(size_t)e * 9];
    }

    uint32_t sA = (uint32_t)__cvta_generic_to_shared(smem) + 4u * (uint32_t)(w * WBUF);
    uint32_t sB = sA + 4u * BUF;

    // Prologue: chunks 0 and 1 in flight (distance 1).
    issue_chunk<0>(sA, p1, p2, pop, W0, lane, elems); cp_commit();
    issue_chunk<1>(sB, p1, p2, pop, W0, lane, elems); cp_commit();

    // Only node 0 of the initial state is nonzero (by construction).
    float sg[9], lg[9];
#pragma unroll
    for (int j = 0; j < 9; j++) { sg[j] = 0.f; lg[j] = 0.f; }
    sg[0] = seed_s;
    lg[0] = seed_l;
    float acc = lg[0] * lg[0];

    const float* rowA = smem + w * WBUF + lane * ST;
    const float* rowB = rowA + BUF;

    // s=0
    cp_wait<1>(); __syncwarp();
    step_compute<0>(rowA, sg, lg, acc);
    __syncwarp();
    issue_chunk<2>(sA, p1, p2, pop, W0, lane, elems); cp_commit();
    // s=1
    cp_wait<1>(); __syncwarp();
    step_compute<1>(rowB, sg, lg, acc);
    __syncwarp();
    issue_chunk<3>(sB, p1, p2, pop, W0, lane, elems); cp_commit();
    // s=2
    cp_wait<1>(); __syncwarp();
    step_compute<2>(rowA, sg, lg, acc);
    __syncwarp();
    issue_chunk<4>(sA, p1, p2, pop, W0, lane, elems); cp_commit();
    // s=3
    cp_wait<1>(); __syncwarp();
    step_compute<3>(rowB, sg, lg, acc);
    __syncwarp();
    issue_chunk<5>(sB, p1, p2, pop, W0, lane, elems); cp_commit();
    // s=4
    cp_wait<1>(); __syncwarp();
    step_compute<4>(rowA, sg, lg, acc);
    __syncwarp();
    issue_chunk<6>(sA, p1, p2, pop, W0, lane, elems); cp_commit();
    // s=5
    cp_wait<1>(); __syncwarp();
    step_compute<5>(rowB, sg, lg, acc);
    __syncwarp();
    issue_chunk<7>(sB, p1, p2, pop, W0, lane, elems); cp_commit();
    // s=6
    cp_wait<1>(); __syncwarp();
    step_compute<6>(rowA, sg, lg, acc);
    // s=7 (drain)
    cp_wait<0>(); __syncwarp();
    step_compute<7>(rowB, sg, lg, acc);

    if (e < elems)
        out[e] = sg[8] * __expf(lg[8]);
}

extern "C" void kernel_launch(void* const* d_in, const int* in_sizes, int n_in,
                              void* d_out, int out_size)
{
    const float* isgn = (const float*)d_in[0];
    const float* ilog = (const float*)d_in[1];
    const float* p1   = (const float*)d_in[2];
    const float* p2   = (const float*)d_in[3];
    const float* pop  = (const float*)d_in[4];
    float* out = (float*)d_out;

    int elems  = in_sizes[0] / 9;               // B*T
    int blocks = (elems + TPB - 1) / TPB;
    dag_kernel<<<blocks, TPB>>>(isgn, ilog, p1, p2, pop, out, elems);
}

// round 11
// speedup vs baseline: 1.6358x; 1.0228x over previous
#include <cuda_runtime.h>
#include <cstdint>

// DifferentiableDAG: B*T independent 8-step log-space DAG executions.
// R10 == R9 resubmitted (R9 bench was an infra failure; kernel never ran).
// R9 = R4 envelope (1 elem/thread, warp-private DOUBLE buffer, distance 1)
// + register/instruction diet (shared exp via monotone clamp, CSE, copysign,
//   warp-level bounds fast path)
// + __launch_bounds__(128,7): 72-reg cap -> 7 blocks = 28 warps/SM.

constexpr int TPB  = 128;
constexpr int ST   = 23;              // floats per smem row (odd => conflict-free)
constexpr int WBUF = 32 * ST;         // floats per warp per buffer (736)
constexpr int BUF  = 4 * WBUF;        // per-block per-buffer (4 warps)

__device__ __forceinline__ void cp_async4(uint32_t saddr, const void* gaddr) {
    asm volatile("cp.async.ca.shared.global [%0], [%1], 4;\n" :: "r"(saddr), "l"(gaddr));
}
__device__ __forceinline__ void cp_commit() { asm volatile("cp.async.commit_group;\n"); }
template<int N>
__device__ __forceinline__ void cp_wait() { asm volatile("cp.async.wait_group %0;\n" :: "n"(N) : "memory"); }

// clip_log(x) = 15*tanh(x/15) via (1-e^{-2z})/(1+e^{-2z})
__device__ __forceinline__ float clip_log(float x) {
    float a = fabsf(x) * (2.0f / 15.0f);
    float t = __expf(-a);
    float u = __fdividef(1.0f - t, 1.0f + t);
    return copysignf(15.0f * u, x);
}

// Stage step S for this warp's 32 elements: p1[0..S], p2[0..S], pop[0..4].
// Warp-level bounds fast path: one test instead of 23 per-element predicates.
template<int S>
__device__ __forceinline__ void issue_chunk(
    uint32_t sbuf, const float* __restrict__ p1, const float* __restrict__ p2,
    const float* __restrict__ pop, int W0, int lane, int elems)
{
    constexpr int NF = S + 1;
    if (W0 + 32 <= elems) {            // full warp in range (always, for this grid)
#pragma unroll
        for (int k = 0; k < NF; k++) {
            int i = lane + 32 * k;
            int e = i / NF, q = i - NF * e;
            int g = (W0 + e) * 72 + S * 9 + q;
            cp_async4(sbuf + 4u * (uint32_t)(e * ST + q),     p1 + g);
            cp_async4(sbuf + 4u * (uint32_t)(e * ST + 9 + q), p2 + g);
        }
#pragma unroll
        for (int k = 0; k < 5; k++) {
            int i = lane + 32 * k;
            int e = i / 5, q = i - 5 * e;
            cp_async4(sbuf + 4u * (uint32_t)(e * ST + 18 + q),
                      pop + (W0 + e) * 40 + S * 5 + q);
        }
    } else {
#pragma unroll
        for (int k = 0; k < NF; k++) {
            int i = lane + 32 * k;
            int e = i / NF, q = i - NF * e;
            if (W0 + e < elems) {
                int g = (W0 + e) * 72 + S * 9 + q;
                cp_async4(sbuf + 4u * (uint32_t)(e * ST + q),     p1 + g);
                cp_async4(sbuf + 4u * (uint32_t)(e * ST + 9 + q), p2 + g);
            }
        }
#pragma unroll
        for (int k = 0; k < 5; k++) {
            int i = lane + 32 * k;
            int e = i / 5, q = i - 5 * e;
            if (W0 + e < elems)
                cp_async4(sbuf + 4u * (uint32_t)(e * ST + 18 + q),
                          pop + (W0 + e) * 40 + S * 5 + q);
        }
    }
}

template<int S>
__device__ __forceinline__ void step_compute(
    const float* __restrict__ row, float (&sg)[9], float (&lg)[9], float& acc)
{
    // ---- dot products over live nodes 0..S ----
    float s1v = 0.f, l1v = 0.f, s2v = 0.f, l2v = 0.f;
#pragma unroll
    for (int n = 0; n <= S; n++) {
        float a = row[n];
        float b = row[9 + n];
        s1v = fmaf(a, sg[n], s1v);
        l1v = fmaf(a, lg[n], l1v);
        s2v = fmaf(b, sg[n], s2v);
        l2v = fmaf(b, lg[n], l2v);
    }
    float po0 = row[18], po1 = row[19], po2 = row[20], po3 = row[21], po4 = row[22];

    // ---- shared log-magnitude pieces (identical for add and sub) ----
    float dlt    = l1v - l2v;
    bool  bigger = (l1v >= l2v);
    float big_l  = bigger ? l1v : l2v;        // == max(l1v,l2v)
    float adlt   = fabsf(dlt);
    float E      = __expf(-adlt);             // exp(-|dlt|), one exp shared
    float l_same = clip_log(big_l + __logf(1.0f + E));
    // exp(clamp(-|dlt|, -15, -0.001)) == clamp(E, e^-15, e^-0.001) (monotone)
    float Ec     = fminf(fmaxf(E, 3.0590232e-07f), 0.99900050f);
    float diffv  = __logf(1.0f - Ec);         // log1p(-exp(delta))
    bool  zr     = (adlt == 0.0f);            // small_l == big_l
    float new_l  = zr ? 0.0f : (big_l + diffv);

    bool  z1 = (s1v == 0.0f), z2 = (s2v == 0.0f);
    float prod = s1v * s2v;
    float s_sgn1 = copysignf(1.0f, s1v);      // only consumed where s1v != 0

    // ---- ADD ----
    float sa = 0.f, la = 0.f;
    {
        bool same_sign = (prod > 0.0f);
        float big_s = bigger ? s1v : s2v;
        float new_s = zr ? 0.0f : big_s;
        if (!z1 &&  z2) { sa = s1v; la = l1v; }
        if ( z1 && !z2) { sa = s2v; la = l2v; }
        if (!z1 && !z2) {
            if (same_sign) { sa = s_sgn1; la = l_same; }
            else           { sa = new_s;  la = new_l;  }
        }
        la = clip_log(la);
    }
    // ---- SUB (sy = -s2v) ----
    float sb = 0.f, lb = 0.f;
    {
        bool same_sign = (prod < 0.0f);
        float sy = -s2v;
        float big_s = bigger ? s1v : sy;
        float new_s = zr ? 0.0f : big_s;
        if (!z1 &&  z2) { sb = s1v; lb = l1v; }
        if ( z1 && !z2) { sb = sy;  lb = l2v; }
        if (!z1 && !z2) {
            if (same_sign) { sb = s_sgn1; lb = l_same; }
            else           { sb = new_s;  lb = new_l;  }
        }
        lb = clip_log(lb);
    }
    // ---- MUL / DIV / ID ----
    float lm = clip_log(l1v + l2v);
    float ld = clip_log(dlt);

    // ---- probability mix ----
    float s_mix = po0 * sa;
    s_mix = fmaf(po1, sb,   s_mix);
    s_mix = fmaf(po2, prod, s_mix);
    s_mix = fmaf(po3, prod, s_mix);
    s_mix = fmaf(po4, s1v,  s_mix);
    float l_mix = po0 * la;
    l_mix = fmaf(po1, lb,  l_mix);
    l_mix = fmaf(po2, lm,  l_mix);
    l_mix = fmaf(po3, ld,  l_mix);
    l_mix = fmaf(po4, l1v, l_mix);
    l_mix = clip_log(l_mix);

    // ---- incremental RMS rescale over logs[0..S] + l_mix ----
    float cur = fmaf(l_mix, l_mix, acc);
    constexpr float inv = 1.0f / (float)(S + 2);
    float r     = rsqrtf(cur * inv + 1e-6f);
    float scale = fminf(15.0f * r, 1.0f);
    l_mix *= scale;

    sg[S + 1] = s_mix;
    lg[S + 1] = l_mix;
    acc = fmaf(l_mix, l_mix, acc);
}

__global__ void __launch_bounds__(TPB, 7)
dag_kernel(const float* __restrict__ isgn, const float* __restrict__ ilog,
           const float* __restrict__ p1,   const float* __restrict__ p2,
           const float* __restrict__ pop,  float* __restrict__ out, int elems)
{
    __shared__ float smem[2 * BUF];      // 23,552 B: double buffer

    const int t    = threadIdx.x;
    const int lane = t & 31;
    const int w    = t >> 5;
    const int E0   = blockIdx.x * TPB;
    const int W0   = E0 + w * 32;        // this warp's first element
    const int e    = W0 + lane;          // this thread's element

    // Hoist the two initial scalar loads so their latency overlaps the prologue.
    float seed_s = 0.f, seed_l = 0.f;
    if (e < elems) {
        seed_s = isgn[(size_t)e * 9];
        seed_l = ilog[(size_t)e * 9];
    }

    uint32_t sA = (uint32_t)__cvta_generic_to_shared(smem) + 4u * (uint32_t)(w * WBUF);
    uint32_t sB = sA + 4u * BUF;

    // Prologue: chunks 0 and 1 in flight (distance 1).
    issue_chunk<0>(sA, p1, p2, pop, W0, lane, elems); cp_commit();
    issue_chunk<1>(sB, p1, p2, pop, W0, lane, elems); cp_commit();

    // Only node 0 of the initial state is nonzero (by construction).
    float sg[9], lg[9];
#pragma unroll
    for (int j = 0; j < 9; j++) { sg[j] = 0.f; lg[j] = 0.f; }
    sg[0] = seed_s;
    lg[0] = seed_l;
    float acc = lg[0] * lg[0];

    const float* rowA = smem + w * WBUF + lane * ST;
    const float* rowB = rowA + BUF;

    // s=0
    cp_wait<1>(); __syncwarp();
    step_compute<0>(rowA, sg, lg, acc);
    __syncwarp();
    issue_chunk<2>(sA, p1, p2, pop, W0, lane, elems); cp_commit();
    // s=1
    cp_wait<1>(); __syncwarp();
    step_compute<1>(rowB, sg, lg, acc);
    __syncwarp();
    issue_chunk<3>(sB, p1, p2, pop, W0, lane, elems); cp_commit();
    // s=2
    cp_wait<1>(); __syncwarp();
    step_compute<2>(rowA, sg, lg, acc);
    __syncwarp();
    issue_chunk<4>(sA, p1, p2, pop, W0, lane, elems); cp_commit();
    // s=3
    cp_wait<1>(); __syncwarp();
    step_compute<3>(rowB, sg, lg, acc);
    __syncwarp();
    issue_chunk<5>(sB, p1, p2, pop, W0, lane, elems); cp_commit();
    // s=4
    cp_wait<1>(); __syncwarp();
    step_compute<4>(rowA, sg, lg, acc);
    __syncwarp();
    issue_chunk<6>(sA, p1, p2, pop, W0, lane, elems); cp_commit();
    // s=5
    cp_wait<1>(); __syncwarp();
    step_compute<5>(rowB, sg, lg, acc);
    __syncwarp();
    issue_chunk<7>(sB, p1, p2, pop, W0, lane, elems); cp_commit();
    // s=6
    cp_wait<1>(); __syncwarp();
    step_compute<6>(rowA, sg, lg, acc);
    // s=7 (drain)
    cp_wait<0>(); __syncwarp();
    step_compute<7>(rowB, sg, lg, acc);

    if (e < elems)
        out[e] = sg[8] * __expf(lg[8]);
}

extern "C" void kernel_launch(void* const* d_in, const int* in_sizes, int n_in,
                              void* d_out, int out_size)
{
    const float* isgn = (const float*)d_in[0];
    const float* ilog = (const float*)d_in[1];
    const float* p1   = (const float*)d_in[2];
    const float* p2   = (const float*)d_in[3];
    const float* pop  = (const float*)d_in[4];
    float* out = (float*)d_out;

    int elems  = in_sizes[0] / 9;               // B*T
    int blocks = (elems + TPB - 1) / TPB;
    dag_kernel<<<blocks, TPB>>>(isgn, ilog, p1, p2, pop, out, elems);
}

// round 14
// speedup vs baseline: 1.9331x; 1.1818x over previous
#include <cuda_runtime.h>
#include <cstdint>

// DifferentiableDAG: B*T independent 8-step log-space DAG executions.
// R14 = R4 envelope (1 elem/thread, warp-private DOUBLE buffer, distance 1,
// __launch_bounds__(128,6) — the proven-stable build) + the R9 instruction
// diet (shared exp via monotone clamp, CSE, copysign, warp-level bounds fast
// path). The R9 source (identical but with a 72-reg cap via min-blocks 7)
// failed container acquisition 4x in a row — suspect pathological ptxas time
// under the cap; this drops only that knob.

constexpr int TPB  = 128;
constexpr int ST   = 23;              // floats per smem row (odd => conflict-free)
constexpr int WBUF = 32 * ST;         // floats per warp per buffer (736)
constexpr int BUF  = 4 * WBUF;        // per-block per-buffer (4 warps)

__device__ __forceinline__ void cp_async4(uint32_t saddr, const void* gaddr) {
    asm volatile("cp.async.ca.shared.global [%0], [%1], 4;\n" :: "r"(saddr), "l"(gaddr));
}
__device__ __forceinline__ void cp_commit() { asm volatile("cp.async.commit_group;\n"); }
template<int N>
__device__ __forceinline__ void cp_wait() { asm volatile("cp.async.wait_group %0;\n" :: "n"(N) : "memory"); }

// clip_log(x) = 15*tanh(x/15) via (1-e^{-2z})/(1+e^{-2z})
__device__ __forceinline__ float clip_log(float x) {
    float a = fabsf(x) * (2.0f / 15.0f);
    float t = __expf(-a);
    float u = __fdividef(1.0f - t, 1.0f + t);
    return copysignf(15.0f * u, x);
}

// Stage step S for this warp's 32 elements: p1[0..S], p2[0..S], pop[0..4].
// Warp-level bounds fast path: one test instead of 23 per-element predicates.
template<int S>
__device__ __forceinline__ void issue_chunk(
    uint32_t sbuf, const float* __restrict__ p1, const float* __restrict__ p2,
    const float* __restrict__ pop, int W0, int lane, int elems)
{
    constexpr int NF = S + 1;
    if (W0 + 32 <= elems) {            // full warp in range (always, for this grid)
#pragma unroll
        for (int k = 0; k < NF; k++) {
            int i = lane + 32 * k;
            int e = i / NF, q = i - NF * e;
            int g = (W0 + e) * 72 + S * 9 + q;
            cp_async4(sbuf + 4u * (uint32_t)(e * ST + q),     p1 + g);
            cp_async4(sbuf + 4u * (uint32_t)(e * ST + 9 + q), p2 + g);
        }
#pragma unroll
        for (int k = 0; k < 5; k++) {
            int i = lane + 32 * k;
            int e = i / 5, q = i - 5 * e;
            cp_async4(sbuf + 4u * (uint32_t)(e * ST + 18 + q),
                      pop + (W0 + e) * 40 + S * 5 + q);
        }
    } else {
#pragma unroll
        for (int k = 0; k < NF; k++) {
            int i = lane + 32 * k;
            int e = i / NF, q = i - NF * e;
            if (W0 + e < elems) {
                int g = (W0 + e) * 72 + S * 9 + q;
                cp_async4(sbuf + 4u * (uint32_t)(e * ST + q),     p1 + g);
                cp_async4(sbuf + 4u * (uint32_t)(e * ST + 9 + q), p2 + g);
            }
        }
#pragma unroll
        for (int k = 0; k < 5; k++) {
            int i = lane + 32 * k;
            int e = i / 5, q = i - 5 * e;
            if (W0 + e < elems)
                cp_async4(sbuf + 4u * (uint32_t)(e * ST + 18 + q),
                          pop + (W0 + e) * 40 + S * 5 + q);
        }
    }
}

template<int S>
__device__ __forceinline__ void step_compute(
    const float* __restrict__ row, float (&sg)[9], float (&lg)[9], float& acc)
{
    // ---- dot products over live nodes 0..S ----
    float s1v = 0.f, l1v = 0.f, s2v = 0.f, l2v = 0.f;
#pragma unroll
    for (int n = 0; n <= S; n++) {
        float a = row[n];
        float b = row[9 + n];
        s1v = fmaf(a, sg[n], s1v);
        l1v = fmaf(a, lg[n], l1v);
        s2v = fmaf(b, sg[n], s2v);
        l2v = fmaf(b, lg[n], l2v);
    }
    float po0 = row[18], po1 = row[19], po2 = row[20], po3 = row[21], po4 = row[22];

    // ---- shared log-magnitude pieces (identical for add and sub) ----
    float dlt    = l1v - l2v;
    bool  bigger = (l1v >= l2v);
    float big_l  = bigger ? l1v : l2v;        // == max(l1v,l2v)
    float adlt   = fabsf(dlt);
    float E      = __expf(-adlt);             // exp(-|dlt|), one exp shared
    float l_same = clip_log(big_l + __logf(1.0f + E));
    // exp(clamp(-|dlt|, -15, -0.001)) == clamp(E, e^-15, e^-0.001) (monotone)
    float Ec     = fminf(fmaxf(E, 3.0590232e-07f), 0.99900050f);
    float diffv  = __logf(1.0f - Ec);         // log1p(-exp(delta))
    bool  zr     = (adlt == 0.0f);            // small_l == big_l
    float new_l  = zr ? 0.0f : (big_l + diffv);

    bool  z1 = (s1v == 0.0f), z2 = (s2v == 0.0f);
    float prod = s1v * s2v;
    float s_sgn1 = copysignf(1.0f, s1v);      // only consumed where s1v != 0

    // ---- ADD ----
    float sa = 0.f, la = 0.f;
    {
        bool same_sign = (prod > 0.0f);
        float big_s = bigger ? s1v : s2v;
        float new_s = zr ? 0.0f : big_s;
        if (!z1 &&  z2) { sa = s1v; la = l1v; }
        if ( z1 && !z2) { sa = s2v; la = l2v; }
        if (!z1 && !z2) {
            if (same_sign) { sa = s_sgn1; la = l_same; }
            else           { sa = new_s;  la = new_l;  }
        }
        la = clip_log(la);
    }
    // ---- SUB (sy = -s2v) ----
    float sb = 0.f, lb = 0.f;
    {
        bool same_sign = (prod < 0.0f);
        float sy = -s2v;
        float big_s = bigger ? s1v : sy;
        float new_s = zr ? 0.0f : big_s;
        if (!z1 &&  z2) { sb = s1v; lb = l1v; }
        if ( z1 && !z2) { sb = sy;  lb = l2v; }
        if (!z1 && !z2) {
            if (same_sign) { sb = s_sgn1; lb = l_same; }
            else           { sb = new_s;  lb = new_l;  }
        }
        lb = clip_log(lb);
    }
    // ---- MUL / DIV / ID ----
    float lm = clip_log(l1v + l2v);
    float ld = clip_log(dlt);

    // ---- probability mix ----
    float s_mix = po0 * sa;
    s_mix = fmaf(po1, sb,   s_mix);
    s_mix = fmaf(po2, prod, s_mix);
    s_mix = fmaf(po3, prod, s_mix);
    s_mix = fmaf(po4, s1v,  s_mix);
    float l_mix = po0 * la;
    l_mix = fmaf(po1, lb,  l_mix);
    l_mix = fmaf(po2, lm,  l_mix);
    l_mix = fmaf(po3, ld,  l_mix);
    l_mix = fmaf(po4, l1v, l_mix);
    l_mix = clip_log(l_mix);

    // ---- incremental RMS rescale over logs[0..S] + l_mix ----
    float cur = fmaf(l_mix, l_mix, acc);
    constexpr float inv = 1.0f / (float)(S + 2);
    float r     = rsqrtf(cur * inv + 1e-6f);
    float scale = fminf(15.0f * r, 1.0f);
    l_mix *= scale;

    sg[S + 1] = s_mix;
    lg[S + 1] = l_mix;
    acc = fmaf(l_mix, l_mix, acc);
}

__global__ void __launch_bounds__(TPB, 6)
dag_kernel(const float* __restrict__ isgn, const float* __restrict__ ilog,
           const float* __restrict__ p1,   const float* __restrict__ p2,
           const float* __restrict__ pop,  float* __restrict__ out, int elems)
{
    __shared__ float smem[2 * BUF];      // 23,552 B: double buffer

    const int t    = threadIdx.x;
    const int lane = t & 31;
    const int w    = t >> 5;
    const int E0   = blockIdx.x * TPB;
    const int W0   = E0 + w * 32;        // this warp's first element
    const int e    = W0 + lane;          // this thread's element

    // Hoist the two initial scalar loads so their latency overlaps the prologue.
    float seed_s = 0.f, seed_l = 0.f;
    if (e < elems) {
        seed_s = isgn[(size_t)e * 9];
        seed_l = ilog[(size_t)e * 9];
    }

    uint32_t sA = (uint32_t)__cvta_generic_to_shared(smem) + 4u * (uint32_t)(w * WBUF);
    uint32_t sB = sA + 4u * BUF;

    // Prologue: chunks 0 and 1 in flight (distance 1).
    issue_chunk<0>(sA, p1, p2, pop, W0, lane, elems); cp_commit();
    issue_chunk<1>(sB, p1, p2, pop, W0, lane, elems); cp_commit();

    // Only node 0 of the initial state is nonzero (by construction).
    float sg[9], lg[9];
#pragma unroll
    for (int j = 0; j < 9; j++) { sg[j] = 0.f; lg[j] = 0.f; }
    sg[0] = seed_s;
    lg[0] = seed_l;
    float acc = lg[0] * lg[0];

    const float* rowA = smem + w * WBUF + lane * ST;
    const float* rowB = rowA + BUF;

    // s=0
    cp_wait<1>(); __syncwarp();
    step_compute<0>(rowA, sg, lg, acc);
    __syncwarp();
    issue_chunk<2>(sA, p1, p2, pop, W0, lane, elems); cp_commit();
    // s=1
    cp_wait<1>(); __syncwarp();
    step_compute<1>(rowB, sg, lg, acc);
    __syncwarp();
    issue_chunk<3>(sB, p1, p2, pop, W0, lane, elems); cp_commit();
    // s=2
    cp_wait<1>(); __syncwarp();
    step_compute<2>(rowA, sg, lg, acc);
    __syncwarp();
    issue_chunk<4>(sA, p1, p2, pop, W0, lane, elems); cp_commit();
    // s=3
    cp_wait<1>(); __syncwarp();
    step_compute<3>(rowB, sg, lg, acc);
    __syncwarp();
    issue_chunk<5>(sB, p1, p2, pop, W0, lane, elems); cp_commit();
    // s=4
    cp_wait<1>(); __syncwarp();
    step_compute<4>(rowA, sg, lg, acc);
    __syncwarp();
    issue_chunk<6>(sA, p1, p2, pop, W0, lane, elems); cp_commit();
    // s=5
    cp_wait<1>(); __syncwarp();
    step_compute<5>(rowB, sg, lg, acc);
    __syncwarp();
    issue_chunk<7>(sB, p1, p2, pop, W0, lane, elems); cp_commit();
    // s=6
    cp_wait<1>(); __syncwarp();
    step_compute<6>(rowA, sg, lg, acc);
    // s=7 (drain)
    cp_wait<0>(); __syncwarp();
    step_compute<7>(rowB, sg, lg, acc);

    if (e < elems)
        out[e] = sg[8] * __expf(lg[8]);
}

extern "C" void kernel_launch(void* const* d_in, const int* in_sizes, int n_in,
                              void* d_out, int out_size)
{
    const float* isgn = (const float*)d_in[0];
    const float* ilog = (const float*)d_in[1];
    const float* p1   = (const float*)d_in[2];
    const float* p2   = (const float*)d_in[3];
    const float* pop  = (const float*)d_in[4];
    float* out = (float*)d_out;

    int elems  = in_sizes[0] / 9;               // B*T
    int blocks = (elems + TPB - 1) / TPB;
    dag_kernel<<<blocks, TPB>>>(isgn, ilog, p1, p2, pop, out, elems);
}